// round 7
// baseline (speedup 1.0000x reference)
#include <cuda_runtime.h>

#define DFT 784
#define DP  800              // padded feature dim (zero-padded tail)
#define PAD 64               // over-allocation so prefetch needs no guard
#define KC  50
#define LF  6
#define NB  2
#define THREADS 128
#define NWARPS (THREADS/32)  // 4 -> warps own 13/13/12/12 components
#define NITER 25             // DP/32
#define STW 30               // padded stats stride

typedef unsigned long long u64;

// SoA packed operands, coalesced per warp:
//  g_C0[k*DP+d] = {c0,c1,c2,c3},  g_C1[k*DP+d] = {c4,c5,s,nsmu},  g_LD[k*DP+d] = logD
// where c_i = sqrt(invD)*a_i, s = sqrt(invD), nsmu = -s*mu.
__device__ __align__(16) float4 g_C0[KC * DP + PAD];
__device__ __align__(16) float4 g_C1[KC * DP + PAD];
__device__ float g_LD[KC * DP + PAD];

__device__ __forceinline__ constexpr int IJ(int i, int j) { return i * (i + 1) / 2 + j; }

// ---- f32x2 packed helpers ----
__device__ __forceinline__ u64 pk2(float a, float b) {
    u64 r; asm("mov.b64 %0,{%1,%2};" : "=l"(r) : "f"(a), "f"(b)); return r;
}
__device__ __forceinline__ u64 rep2(float a) { return pk2(a, a); }
__device__ __forceinline__ void upk2(u64 v, float& a, float& b) {
    asm("mov.b64 {%0,%1},%2;" : "=f"(a), "=f"(b) : "l"(v));
}
__device__ __forceinline__ u64 fma2(u64 a, u64 b, u64 c) {
    u64 d; asm("fma.rn.f32x2 %0,%1,%2,%3;" : "=l"(d) : "l"(a), "l"(b), "l"(c)); return d;
}
__device__ __forceinline__ u64 add2(u64 a, u64 b) {
    u64 d; asm("add.rn.f32x2 %0,%1,%2;" : "=l"(d) : "l"(a), "l"(b)); return d;
}

__global__ void pack_kernel(const float* __restrict__ A_fac,
                            const float* __restrict__ MU,
                            const float* __restrict__ log_D)
{
    int idx = blockIdx.x * blockDim.x + threadIdx.x;
    if (idx >= KC * DP + PAD) return;
    int k = idx / DP, d = idx - k * DP;
    if (k < KC && d < DFT) {
        int src = k * DFT + d;
        const float* a = A_fac + (size_t)src * LF;
        float ld = log_D[src];
        float s  = expf(-0.5f * ld);       // sqrt(invD)
        g_C0[idx] = make_float4(s * a[0], s * a[1], s * a[2], s * a[3]);
        g_C1[idx] = make_float4(s * a[4], s * a[5], s, -s * MU[src]);
        g_LD[idx] = ld;
    } else {
        g_C0[idx] = make_float4(0.f, 0.f, 0.f, 0.f);
        g_C1[idx] = make_float4(0.f, 0.f, 0.f, 0.f);
        g_LD[idx] = 0.f;
    }
}

// Cholesky (lower) of packed 6x6 SPD, in place. Returns product of pivots (= det),
// fills inv[j] = 1/L[j][j].
__device__ __forceinline__ float chol6(float* S, float* inv)
{
    float prod = 1.f;
    #pragma unroll
    for (int j = 0; j < LF; j++) {
        float s = S[IJ(j, j)];
        #pragma unroll
        for (int m = 0; m < j; m++) s = fmaf(-S[IJ(j, m)], S[IJ(j, m)], s);
        prod *= s;
        float rs = rsqrtf(s);
        inv[j] = rs;
        S[IJ(j, j)] = s * rs;
        #pragma unroll
        for (int i = j + 1; i < LF; i++) {
            float t = S[IJ(i, j)];
            #pragma unroll
            for (int m = 0; m < j; m++) t = fmaf(-S[IJ(i, m)], S[IJ(j, m)], t);
            S[IJ(i, j)] = t * rs;
        }
    }
    return prod;
}

__device__ __forceinline__ float fwd6(const float* L, const float* inv, const float* q, float* y)
{
    float ysq = 0.f;
    #pragma unroll
    for (int i = 0; i < LF; i++) {
        float t = q[i];
        #pragma unroll
        for (int m = 0; m < i; m++) t = fmaf(-L[IJ(i, m)], y[m], t);
        y[i] = t * inv[i];
        ysq = fmaf(y[i], y[i], ysq);
    }
    return ysq;
}

// Prefetch slots carry only the two LDG.128 streams (L2-latency bound).
struct Slot { float4 v0, v1; };

__device__ __forceinline__ void load_slot(Slot& s, const float4* __restrict__ p0,
                                          const float4* __restrict__ p1, int d)
{
    s.v0 = p0[d]; s.v1 = p1[d];
}

// in.x = {mask0, mask1} (0x0 / 0xFFFFFFFF per sample), in.y = {xj0, xj1}
__device__ __forceinline__ void consume(const Slot& c, float ld, ulonglong2 in, u64* acc)
{
    const u64 mask2 = in.x;
    const u64 xj2   = in.y;
    u64 c2[LF] = { rep2(c.v0.x), rep2(c.v0.y), rep2(c.v0.z),
                   rep2(c.v0.w), rep2(c.v1.x), rep2(c.v1.y) };

    // e = s*xj + (nsmu masked): 1 FMA + AND
    u64 e2 = fma2(rep2(c.v1.z), xj2, rep2(c.v1.w) & mask2);
    acc[27] = fma2(e2, e2, acc[27]);                 // quad
    acc[28] = add2(rep2(ld) & mask2, acc[28]);       // Jf . logD

    u64 g2[LF];
    #pragma unroll
    for (int i = 0; i < LF; i++) g2[i] = c2[i] & mask2;   // jf * c_i (exact, ALU pipe)

    #pragma unroll
    for (int i = 0; i < LF; i++) {
        acc[21 + i] = fma2(e2, c2[i], acc[21 + i]);       // q (e already masked)
        #pragma unroll
        for (int j = 0; j <= i; j++)
            acc[IJ(i, j)] = fma2(g2[i], c2[j], acc[IJ(i, j)]);  // P
    }
}

__global__ __launch_bounds__(THREADS, 4)
void mfa_main(const float* __restrict__ X, const int* __restrict__ J,
              const float* __restrict__ MU, const float* __restrict__ A_fac,
              const float* __restrict__ log_D, const float* __restrict__ PI,
              float* __restrict__ outPw, float* __restrict__ outM,
              float* __restrict__ outA, float* __restrict__ outD)
{
    __shared__ ulonglong2 s_in[DP + PAD];      // {maskpair, xjpair}
    __shared__ float  s_pi[KC];
    __shared__ float  s_stats[KC][NB][STW];    // raw sums: P 21, q 6, quad, jlogd
    __shared__ float  s_score[KC * NB];
    __shared__ float  s_mz[NB][LF];
    __shared__ float  s_Lzm[NB][21];
    __shared__ int    s_c[NB];

    const int tid  = threadIdx.x;
    const int lane = tid & 31;
    const int warp = tid >> 5;
    const int b0   = blockIdx.x * NB;

    for (int t = tid; t < DP + PAD; t += THREADS) {
        if (t < DFT) {
            float x0  = X[(size_t)b0 * DFT + t];
            float x1  = X[(size_t)(b0 + 1) * DFT + t];
            bool  j0  = (J[(size_t)b0 * DFT + t] == 1);
            bool  j1  = (J[(size_t)(b0 + 1) * DFT + t] == 1);
            unsigned m0 = j0 ? 0xffffffffu : 0u;
            unsigned m1 = j1 ? 0xffffffffu : 0u;
            float xj0 = j0 ? x0 : 0.0f;
            float xj1 = j1 ? x1 : 0.0f;
            ulonglong2 v;
            v.x = (u64)m0 | ((u64)m1 << 32);
            v.y = (u64)__float_as_uint(xj0) | ((u64)__float_as_uint(xj1) << 32);
            s_in[t] = v;
        } else {
            s_in[t] = make_ulonglong2(0ull, 0ull);
        }
    }
    for (int t = tid; t < KC; t += THREADS) s_pi[t] = PI[t];
    __syncthreads();

    // ---- Phase 1: accumulate raw stats; warp w owns k = w, w+4, ... ----
    for (int k = warp; k < KC; k += NWARPS) {
        u64 acc[29];
        #pragma unroll
        for (int t = 0; t < 29; t++) acc[t] = 0ull;

        const float4* __restrict__ p0 = g_C0 + (size_t)k * DP;
        const float4* __restrict__ p1 = g_C1 + (size_t)k * DP;
        const float*  __restrict__ pl = g_LD + (size_t)k * DP;

        Slot s0, s1;
        load_slot(s0, p0, p1, lane);
        load_slot(s1, p0, p1, lane + 32);

        #pragma unroll 2
        for (int t = 0; t < NITER - 1; t += 2) {
            int d = lane + 32 * t;
            Slot c0 = s0;
            load_slot(s0, p0, p1, d + 64);
            consume(c0, pl[d], s_in[d], acc);
            Slot c1 = s1;
            load_slot(s1, p0, p1, d + 96);
            consume(c1, pl[d + 32], s_in[d + 32], acc);
        }
        {
            int d = lane + 32 * (NITER - 1);
            consume(s0, pl[d], s_in[d], acc);
        }

        // Split-sample reduction: xor-1 exchange of packed pair; even lanes keep
        // sample-0 partials, odd lanes sample-1; then fp32 butterflies.
        const bool odd = (lane & 1);
        float r[29];
        #pragma unroll
        for (int t = 0; t < 29; t++) {
            u64 o = __shfl_xor_sync(0xffffffffu, acc[t], 1);
            float slo, shi, olo, ohi;
            upk2(acc[t], slo, shi);
            upk2(o, olo, ohi);
            r[t] = odd ? (shi + ohi) : (slo + olo);
        }
        #pragma unroll
        for (int t = 0; t < 29; t++) {
            #pragma unroll
            for (int off = 2; off < 32; off <<= 1)
                r[t] += __shfl_xor_sync(0xffffffffu, r[t], off);
        }
        if (lane < 2) {
            #pragma unroll
            for (int t = 0; t < 29; t++) s_stats[k][lane][t] = r[t];
        }
    }
    __syncthreads();

    // ---- Phase 1.5: block-parallel scoring (100 independent tasks) ----
    if (tid < KC * NB) {
        const int k  = tid >> 1;
        const int b2 = tid & 1;
        float P[21], q[LF];
        #pragma unroll
        for (int t = 0; t < 21; t++) P[t] = s_stats[k][b2][t];
        float quad = s_stats[k][b2][27];
        float jld  = s_stats[k][b2][28];
        #pragma unroll
        for (int i = 0; i < LF; i++) { P[IJ(i, i)] += 1.0f; q[i] = s_stats[k][b2][21 + i]; }
        float inv[LF];
        float prod = chol6(P, inv);
        float y[LF];
        float ysq = fwd6(P, inv, q, y);
        s_score[tid] = s_pi[k] - 0.5f * (quad - ysq + __logf(prod) + jld);
    }
    __syncthreads();

    // ---- Phase 2: select winner (ascending k => first-max) + small linalg ----
    if (tid < NB) {
        const int b2 = tid;
        float best = -1e30f; int bc = 0;
        for (int k = 0; k < KC; k++) {
            float sc = s_score[k * NB + b2];
            if (sc > best) { best = sc; bc = k; }
        }
        s_c[b2] = bc;

        float P[21], q[LF];
        #pragma unroll
        for (int t = 0; t < 21; t++) P[t] = s_stats[bc][b2][t];
        #pragma unroll
        for (int i = 0; i < LF; i++) { P[IJ(i, i)] += 1.0f; q[i] = s_stats[bc][b2][21 + i]; }

        float inv[LF];
        (void)chol6(P, inv);
        float y[LF];
        (void)fwd6(P, inv, q, y);
        float mz[LF];
        #pragma unroll
        for (int ii = LF - 1; ii >= 0; ii--) {
            float t = y[ii];
            #pragma unroll
            for (int m = ii + 1; m < LF; m++) t = fmaf(-P[IJ(m, ii)], mz[m], t);
            mz[ii] = t * inv[ii];
        }
        float Li[21];
        #pragma unroll
        for (int j = 0; j < LF; j++) {
            Li[IJ(j, j)] = inv[j];
            #pragma unroll
            for (int i = j + 1; i < LF; i++) {
                float t = 0.f;
                #pragma unroll
                for (int m = j; m < i; m++) t = fmaf(P[IJ(i, m)], Li[IJ(m, j)], t);
                Li[IJ(i, j)] = -inv[i] * t;
            }
        }
        float C[21];
        #pragma unroll
        for (int i = 0; i < LF; i++)
            #pragma unroll
            for (int j = 0; j <= i; j++) {
                float t = 0.f;
                #pragma unroll
                for (int m = i; m < LF; m++) t = fmaf(Li[IJ(m, i)], Li[IJ(m, j)], t);
                C[IJ(i, j)] = t;
            }
        float invz[LF];
        (void)chol6(C, invz);
        #pragma unroll
        for (int i = 0; i < LF; i++) s_mz[b2][i] = mz[i];
        #pragma unroll
        for (int t = 0; t < 21; t++) s_Lzm[b2][t] = C[t];
    }
    __syncthreads();

    // ---- Epilogue: stream outputs (exact original inputs) ----
    #pragma unroll
    for (int b2 = 0; b2 < NB; b2++) {
        const int b = b0 + b2;
        const int c = s_c[b2];
        float mz[LF], Lz[21];
        #pragma unroll
        for (int i = 0; i < LF; i++) mz[i] = s_mz[b2][i];
        #pragma unroll
        for (int t = 0; t < 21; t++) Lz[t] = s_Lzm[b2][t];
        const float* __restrict__ ac  = A_fac + (size_t)c * DFT * LF;
        const float* __restrict__ muc = MU    + (size_t)c * DFT;
        const float* __restrict__ ldc = log_D + (size_t)c * DFT;
        for (int d = tid; d < DFT; d += THREADS) {
            const float2* ar = reinterpret_cast<const float2*>(ac + (size_t)d * LF);
            float2 r0 = ar[0], r1 = ar[1], r2 = ar[2];
            float a[LF] = {r0.x, r0.y, r1.x, r1.y, r2.x, r2.y};
            float Mo = muc[d];
            #pragma unroll
            for (int i = 0; i < LF; i++) Mo = fmaf(a[i], mz[i], Mo);
            outM[(size_t)b * DFT + d] = Mo;
            float Ao[LF];
            #pragma unroll
            for (int j = 0; j < LF; j++) {
                float s = 0.f;
                #pragma unroll
                for (int i = j; i < LF; i++) s = fmaf(a[i], Lz[IJ(i, j)], s);
                Ao[j] = s;
            }
            float2* pA = reinterpret_cast<float2*>(outA + ((size_t)b * DFT + d) * LF);
            pA[0] = make_float2(Ao[0], Ao[1]);
            pA[1] = make_float2(Ao[2], Ao[3]);
            pA[2] = make_float2(Ao[4], Ao[5]);
            outD[(size_t)b * DFT + d] = expf(ldc[d]);
        }
    }
    if (tid < NB) outPw[b0 + tid] = 1.0f;
}

extern "C" void kernel_launch(void* const* d_in, const int* in_sizes, int n_in,
                              void* d_out, int out_size)
{
    const float* X      = (const float*)d_in[0];
    const int*   J      = (const int*)  d_in[1];
    const float* MU     = (const float*)d_in[2];
    const float* A_fac  = (const float*)d_in[3];
    const float* log_D  = (const float*)d_in[4];
    const float* PI     = (const float*)d_in[5];
    float* out = (float*)d_out;

    const int B = in_sizes[0] / DFT;     // 2048
    float* outPw = out;
    float* outM  = out + B;
    float* outA  = outM + (size_t)B * DFT;
    float* outD  = outA + (size_t)B * DFT * LF;

    pack_kernel<<<(KC * DP + PAD + 255) / 256, 256>>>(A_fac, MU, log_D);
    mfa_main<<<B / NB, THREADS>>>(X, J, MU, A_fac, log_D, PI, outPw, outM, outA, outD);
}

// round 8
// speedup vs baseline: 1.0245x; 1.0245x over previous
#include <cuda_runtime.h>

#define DFT 784
#define DP  800              // padded feature dim (zero-padded tail)
#define PAD 64               // over-allocation so prefetch needs no guard
#define KC  50
#define LF  6
#define NB  2
#define THREADS 128
#define NWARPS (THREADS/32)  // 4 -> warps own 13/13/12/12 components
#define NITER 25             // DP/32
#define STW 30               // padded stats stride

typedef unsigned long long u64;

// SoA packed operands, coalesced per warp; pair-replicated where a broadcast
// is needed so f32x2 register pairs load directly from memory:
//  g_G0[k*DP+d] = {c0,c1,c2,c3}
//  g_G1[k*DP+d] = {c4,c5, ld,ld}
//  g_G2[k*DP+d] = {s,s, nsmu,nsmu}
// where c_i = sqrt(invD)*a_i, s = sqrt(invD), nsmu = -s*mu, ld = logD.
__device__ __align__(16) float4 g_G0[KC * DP + PAD];
__device__ __align__(16) float4 g_G1[KC * DP + PAD];
__device__ __align__(16) float4 g_G2[KC * DP + PAD];

__device__ __forceinline__ constexpr int IJ(int i, int j) { return i * (i + 1) / 2 + j; }

// ---- f32x2 packed helpers ----
__device__ __forceinline__ u64 pk2(float a, float b) {
    u64 r; asm("mov.b64 %0,{%1,%2};" : "=l"(r) : "f"(a), "f"(b)); return r;
}
__device__ __forceinline__ u64 rep2(float a) { return pk2(a, a); }
__device__ __forceinline__ void upk2(u64 v, float& a, float& b) {
    asm("mov.b64 {%0,%1},%2;" : "=f"(a), "=f"(b) : "l"(v));
}
__device__ __forceinline__ u64 fma2(u64 a, u64 b, u64 c) {
    u64 d; asm("fma.rn.f32x2 %0,%1,%2,%3;" : "=l"(d) : "l"(a), "l"(b), "l"(c)); return d;
}
__device__ __forceinline__ u64 mul2(u64 a, u64 b) {
    u64 d; asm("mul.rn.f32x2 %0,%1,%2;" : "=l"(d) : "l"(a), "l"(b)); return d;
}

__global__ void pack_kernel(const float* __restrict__ A_fac,
                            const float* __restrict__ MU,
                            const float* __restrict__ log_D)
{
    int idx = blockIdx.x * blockDim.x + threadIdx.x;
    if (idx >= KC * DP + PAD) return;
    int k = idx / DP, d = idx - k * DP;
    if (k < KC && d < DFT) {
        int src = k * DFT + d;
        const float* a = A_fac + (size_t)src * LF;
        float ld = log_D[src];
        float s  = expf(-0.5f * ld);       // sqrt(invD)
        float nsmu = -s * MU[src];
        g_G0[idx] = make_float4(s * a[0], s * a[1], s * a[2], s * a[3]);
        g_G1[idx] = make_float4(s * a[4], s * a[5], ld, ld);
        g_G2[idx] = make_float4(s, s, nsmu, nsmu);
    } else {
        g_G0[idx] = make_float4(0.f, 0.f, 0.f, 0.f);
        g_G1[idx] = make_float4(0.f, 0.f, 0.f, 0.f);
        g_G2[idx] = make_float4(0.f, 0.f, 0.f, 0.f);
    }
}

// Cholesky (lower) of packed 6x6 SPD, in place. Returns product of pivots (= det),
// fills inv[j] = 1/L[j][j].
__device__ __forceinline__ float chol6(float* S, float* inv)
{
    float prod = 1.f;
    #pragma unroll
    for (int j = 0; j < LF; j++) {
        float s = S[IJ(j, j)];
        #pragma unroll
        for (int m = 0; m < j; m++) s = fmaf(-S[IJ(j, m)], S[IJ(j, m)], s);
        prod *= s;
        float rs = rsqrtf(s);
        inv[j] = rs;
        S[IJ(j, j)] = s * rs;
        #pragma unroll
        for (int i = j + 1; i < LF; i++) {
            float t = S[IJ(i, j)];
            #pragma unroll
            for (int m = 0; m < j; m++) t = fmaf(-S[IJ(i, m)], S[IJ(j, m)], t);
            S[IJ(i, j)] = t * rs;
        }
    }
    return prod;
}

__device__ __forceinline__ float fwd6(const float* L, const float* inv, const float* q, float* y)
{
    float ysq = 0.f;
    #pragma unroll
    for (int i = 0; i < LF; i++) {
        float t = q[i];
        #pragma unroll
        for (int m = 0; m < i; m++) t = fmaf(-L[IJ(i, m)], y[m], t);
        y[i] = t * inv[i];
        ysq = fmaf(y[i], y[i], ysq);
    }
    return ysq;
}

// Prefetch slots carry the three LDG.128 streams.
struct Slot { float4 g0, g1, g2; };

__device__ __forceinline__ void load_slot(Slot& s, const float4* __restrict__ p0,
                                          const float4* __restrict__ p1,
                                          const float4* __restrict__ p2, int d)
{
    s.g0 = p0[d]; s.g1 = p1[d]; s.g2 = p2[d];
}

__device__ __forceinline__ void consume(const Slot& c, float4 in, u64* acc)
{
    // pairs straight from registers: jf2={in.x,in.y}, xj2={in.z,in.w},
    // ld2={g1.z,g1.w}, s2={g2.x,g2.y}, nsmu2={g2.z,g2.w}
    u64 jf2   = pk2(in.x, in.y);
    u64 xj2   = pk2(in.z, in.w);
    u64 ld2   = pk2(c.g1.z, c.g1.w);
    u64 s2    = pk2(c.g2.x, c.g2.y);
    u64 nsmu2 = pk2(c.g2.z, c.g2.w);
    u64 c2[LF] = { rep2(c.g0.x), rep2(c.g0.y), rep2(c.g0.z),
                   rep2(c.g0.w), rep2(c.g1.x), rep2(c.g1.y) };

    u64 e2 = fma2(nsmu2, jf2, mul2(s2, xj2));      // sqrt(invD)*masked residual
    acc[27] = fma2(e2, e2, acc[27]);               // quad
    acc[28] = fma2(jf2, ld2, acc[28]);             // Jf . logD

    #pragma unroll
    for (int i = 0; i < LF; i++) {
        acc[21 + i] = fma2(e2, c2[i], acc[21 + i]);    // q
        u64 ja = mul2(jf2, c2[i]);
        #pragma unroll
        for (int j = 0; j <= i; j++)
            acc[IJ(i, j)] = fma2(ja, c2[j], acc[IJ(i, j)]);  // P
    }
}

__global__ __launch_bounds__(THREADS, 4)
void mfa_main(const float* __restrict__ X, const int* __restrict__ J,
              const float* __restrict__ MU, const float* __restrict__ A_fac,
              const float* __restrict__ log_D, const float* __restrict__ PI,
              float* __restrict__ outPw, float* __restrict__ outM,
              float* __restrict__ outA, float* __restrict__ outD)
{
    __shared__ float4 s_in[DP + PAD];          // {jf0, jf1, xj0, xj1}
    __shared__ float  s_pi[KC];
    __shared__ float  s_stats[KC][NB][STW];    // raw sums: P 21, q 6, quad, jlogd
    __shared__ float  s_score[KC * NB];
    __shared__ float  s_mz[NB][LF];
    __shared__ float  s_Lzm[NB][21];
    __shared__ int    s_c[NB];

    const int tid  = threadIdx.x;
    const int lane = tid & 31;
    const int warp = tid >> 5;
    const int b0   = blockIdx.x * NB;

    for (int t = tid; t < DP + PAD; t += THREADS) {
        if (t < DFT) {
            float x0  = X[(size_t)b0 * DFT + t];
            float x1  = X[(size_t)(b0 + 1) * DFT + t];
            float jf0 = (J[(size_t)b0 * DFT + t] == 1) ? 1.0f : 0.0f;
            float jf1 = (J[(size_t)(b0 + 1) * DFT + t] == 1) ? 1.0f : 0.0f;
            s_in[t] = make_float4(jf0, jf1, x0 * jf0, x1 * jf1);
        } else {
            s_in[t] = make_float4(0.f, 0.f, 0.f, 0.f);
        }
    }
    for (int t = tid; t < KC; t += THREADS) s_pi[t] = PI[t];
    __syncthreads();

    // ---- Phase 1: accumulate raw stats; warp w owns k = w, w+4, ... ----
    for (int k = warp; k < KC; k += NWARPS) {
        u64 acc[29];
        #pragma unroll
        for (int t = 0; t < 29; t++) acc[t] = 0ull;

        const float4* __restrict__ p0 = g_G0 + (size_t)k * DP;
        const float4* __restrict__ p1 = g_G1 + (size_t)k * DP;
        const float4* __restrict__ p2 = g_G2 + (size_t)k * DP;

        Slot s0, s1;
        load_slot(s0, p0, p1, p2, lane);
        load_slot(s1, p0, p1, p2, lane + 32);

        #pragma unroll 2
        for (int t = 0; t < NITER - 1; t += 2) {
            int d = lane + 32 * t;
            Slot c0 = s0;
            load_slot(s0, p0, p1, p2, d + 64);
            consume(c0, s_in[d], acc);
            Slot c1 = s1;
            load_slot(s1, p0, p1, p2, d + 96);
            consume(c1, s_in[d + 32], acc);
        }
        {
            int d = lane + 32 * (NITER - 1);
            consume(s0, s_in[d], acc);
        }

        // Split-sample reduction: xor-1 exchange of packed pair; even lanes keep
        // sample-0 partials, odd lanes sample-1; then fp32 butterflies.
        const bool odd = (lane & 1);
        float r[29];
        #pragma unroll
        for (int t = 0; t < 29; t++) {
            u64 o = __shfl_xor_sync(0xffffffffu, acc[t], 1);
            float slo, shi, olo, ohi;
            upk2(acc[t], slo, shi);
            upk2(o, olo, ohi);
            r[t] = odd ? (shi + ohi) : (slo + olo);
        }
        #pragma unroll
        for (int t = 0; t < 29; t++) {
            #pragma unroll
            for (int off = 2; off < 32; off <<= 1)
                r[t] += __shfl_xor_sync(0xffffffffu, r[t], off);
        }
        if (lane < 2) {
            #pragma unroll
            for (int t = 0; t < 29; t++) s_stats[k][lane][t] = r[t];
        }
    }
    __syncthreads();

    // ---- Phase 1.5: block-parallel scoring (100 independent tasks) ----
    if (tid < KC * NB) {
        const int k  = tid >> 1;
        const int b2 = tid & 1;
        float P[21], q[LF];
        #pragma unroll
        for (int t = 0; t < 21; t++) P[t] = s_stats[k][b2][t];
        float quad = s_stats[k][b2][27];
        float jld  = s_stats[k][b2][28];
        #pragma unroll
        for (int i = 0; i < LF; i++) { P[IJ(i, i)] += 1.0f; q[i] = s_stats[k][b2][21 + i]; }
        float inv[LF];
        float prod = chol6(P, inv);
        float y[LF];
        float ysq = fwd6(P, inv, q, y);
        s_score[tid] = s_pi[k] - 0.5f * (quad - ysq + __logf(prod) + jld);
    }
    __syncthreads();

    // ---- Phase 2: select winner (ascending k => first-max) + small linalg ----
    if (tid < NB) {
        const int b2 = tid;
        float best = -1e30f; int bc = 0;
        for (int k = 0; k < KC; k++) {
            float sc = s_score[k * NB + b2];
            if (sc > best) { best = sc; bc = k; }
        }
        s_c[b2] = bc;

        float P[21], q[LF];
        #pragma unroll
        for (int t = 0; t < 21; t++) P[t] = s_stats[bc][b2][t];
        #pragma unroll
        for (int i = 0; i < LF; i++) { P[IJ(i, i)] += 1.0f; q[i] = s_stats[bc][b2][21 + i]; }

        float inv[LF];
        (void)chol6(P, inv);
        float y[LF];
        (void)fwd6(P, inv, q, y);
        float mz[LF];
        #pragma unroll
        for (int ii = LF - 1; ii >= 0; ii--) {
            float t = y[ii];
            #pragma unroll
            for (int m = ii + 1; m < LF; m++) t = fmaf(-P[IJ(m, ii)], mz[m], t);
            mz[ii] = t * inv[ii];
        }
        float Li[21];
        #pragma unroll
        for (int j = 0; j < LF; j++) {
            Li[IJ(j, j)] = inv[j];
            #pragma unroll
            for (int i = j + 1; i < LF; i++) {
                float t = 0.f;
                #pragma unroll
                for (int m = j; m < i; m++) t = fmaf(P[IJ(i, m)], Li[IJ(m, j)], t);
                Li[IJ(i, j)] = -inv[i] * t;
            }
        }
        float C[21];
        #pragma unroll
        for (int i = 0; i < LF; i++)
            #pragma unroll
            for (int j = 0; j <= i; j++) {
                float t = 0.f;
                #pragma unroll
                for (int m = i; m < LF; m++) t = fmaf(Li[IJ(m, i)], Li[IJ(m, j)], t);
                C[IJ(i, j)] = t;
            }
        float invz[LF];
        (void)chol6(C, invz);
        #pragma unroll
        for (int i = 0; i < LF; i++) s_mz[b2][i] = mz[i];
        #pragma unroll
        for (int t = 0; t < 21; t++) s_Lzm[b2][t] = C[t];
    }
    __syncthreads();

    // ---- Epilogue: stream outputs (exact original inputs) ----
    #pragma unroll
    for (int b2 = 0; b2 < NB; b2++) {
        const int b = b0 + b2;
        const int c = s_c[b2];
        float mz[LF], Lz[21];
        #pragma unroll
        for (int i = 0; i < LF; i++) mz[i] = s_mz[b2][i];
        #pragma unroll
        for (int t = 0; t < 21; t++) Lz[t] = s_Lzm[b2][t];
        const float* __restrict__ ac  = A_fac + (size_t)c * DFT * LF;
        const float* __restrict__ muc = MU    + (size_t)c * DFT;
        const float* __restrict__ ldc = log_D + (size_t)c * DFT;
        for (int d = tid; d < DFT; d += THREADS) {
            const float2* ar = reinterpret_cast<const float2*>(ac + (size_t)d * LF);
            float2 r0 = ar[0], r1 = ar[1], r2 = ar[2];
            float a[LF] = {r0.x, r0.y, r1.x, r1.y, r2.x, r2.y};
            float Mo = muc[d];
            #pragma unroll
            for (int i = 0; i < LF; i++) Mo = fmaf(a[i], mz[i], Mo);
            outM[(size_t)b * DFT + d] = Mo;
            float Ao[LF];
            #pragma unroll
            for (int j = 0; j < LF; j++) {
                float s = 0.f;
                #pragma unroll
                for (int i = j; i < LF; i++) s = fmaf(a[i], Lz[IJ(i, j)], s);
                Ao[j] = s;
            }
            float2* pA = reinterpret_cast<float2*>(outA + ((size_t)b * DFT + d) * LF);
            pA[0] = make_float2(Ao[0], Ao[1]);
            pA[1] = make_float2(Ao[2], Ao[3]);
            pA[2] = make_float2(Ao[4], Ao[5]);
            outD[(size_t)b * DFT + d] = expf(ldc[d]);
        }
    }
    if (tid < NB) outPw[b0 + tid] = 1.0f;
}

extern "C" void kernel_launch(void* const* d_in, const int* in_sizes, int n_in,
                              void* d_out, int out_size)
{
    const float* X      = (const float*)d_in[0];
    const int*   J      = (const int*)  d_in[1];
    const float* MU     = (const float*)d_in[2];
    const float* A_fac  = (const float*)d_in[3];
    const float* log_D  = (const float*)d_in[4];
    const float* PI     = (const float*)d_in[5];
    float* out = (float*)d_out;

    const int B = in_sizes[0] / DFT;     // 2048
    float* outPw = out;
    float* outM  = out + B;
    float* outA  = outM + (size_t)B * DFT;
    float* outD  = outA + (size_t)B * DFT * LF;

    pack_kernel<<<(KC * DP + PAD + 255) / 256, 256>>>(A_fac, MU, log_D);
    mfa_main<<<B / NB, THREADS>>>(X, J, MU, A_fac, log_D, PI, outPw, outM, outA, outD);
}